// round 4
// baseline (speedup 1.0000x reference)
#include <cuda_runtime.h>
#include <math.h>

// Problem constants (fixed by setup_inputs)
#define BB   2
#define TT   2048
#define CC   1024
#define HH   16
#define HKVV 4
#define DD   64
#define MM   (BB*TT)          // 4096 rows
#define KVD  (HKVV*DD)        // 256

// GEMM tiling
#define BM 128
#define BN 128
#define BK 16

// Attention tiling
#define AQ 128   // query rows per CTA (1 thread = 1 row)
#define AK 64    // keys per smem tile

// ---------------- scratch (static device globals; no allocs allowed) --------
__device__ float g_q[MM * CC];      // 16 MB
__device__ float g_k[MM * KVD];     // 4 MB
__device__ float g_v[MM * KVD];     // 4 MB
__device__ float g_att[MM * CC];    // 16 MB
__device__ float g_cos[TT][8];
__device__ float g_sin[TT][8];

// ---------------- RoPE table (double precision of fp32 angle) ---------------
__global__ void rope_table_kernel() {
    int idx = blockIdx.x * blockDim.x + threadIdx.x;   // 0 .. TT*8-1
    if (idx >= TT * 8) return;
    int t = idx >> 3;
    int i = idx & 7;
    // inv_freq[i] = 10000^(-(2i)/64), rounded to fp32 like the reference
    double inv_d = exp2(-((double)(2 * i) / 64.0) * 13.28771237954945);  // log2(10000)
    float inv_f = (float)inv_d;
    float ang = (float)t * inv_f;              // fp32 product, like jnp.outer
    g_cos[t][i] = (float)cos((double)ang);
    g_sin[t][i] = (float)sin((double)ang);
}

// ---------------- generic fp32 GEMM tile:  Y = A @ W^T -----------------------
// A row-major [*, K] (stride K), W row-major [N, K] (stride K), Y stride ldy.
__device__ __forceinline__ void gemm_tile(
    const float* __restrict__ A, const float* __restrict__ W,
    float* __restrict__ Y, int ldy, int m0, int n0w, int n0y, int K,
    float (*As)[BM], float (*Bs)[BN])
{
    int tid = threadIdx.x;                 // 0..255
    int tx = tid & 15, ty = tid >> 4;      // 16 x 16 thread grid, 8x8 micro-tile

    float acc[8][8];
#pragma unroll
    for (int i = 0; i < 8; i++)
#pragma unroll
        for (int j = 0; j < 8; j++) acc[i][j] = 0.f;

    int lr = tid >> 1;            // load row 0..127
    int lk = (tid & 1) * 8;       // k offset 0 or 8

    const float* Aptr = A + (size_t)(m0 + lr) * K + lk;
    const float* Wptr = W + (size_t)(n0w + lr) * K + lk;

    for (int k0 = 0; k0 < K; k0 += BK) {
        float4 a0 = *(const float4*)(Aptr + k0);
        float4 a1 = *(const float4*)(Aptr + k0 + 4);
        float4 b0 = *(const float4*)(Wptr + k0);
        float4 b1 = *(const float4*)(Wptr + k0 + 4);
        __syncthreads();
        As[lk+0][lr]=a0.x; As[lk+1][lr]=a0.y; As[lk+2][lr]=a0.z; As[lk+3][lr]=a0.w;
        As[lk+4][lr]=a1.x; As[lk+5][lr]=a1.y; As[lk+6][lr]=a1.z; As[lk+7][lr]=a1.w;
        Bs[lk+0][lr]=b0.x; Bs[lk+1][lr]=b0.y; Bs[lk+2][lr]=b0.z; Bs[lk+3][lr]=b0.w;
        Bs[lk+4][lr]=b1.x; Bs[lk+5][lr]=b1.y; Bs[lk+6][lr]=b1.z; Bs[lk+7][lr]=b1.w;
        __syncthreads();
#pragma unroll
        for (int kk = 0; kk < BK; kk++) {
            float af[8], bf[8];
            *(float4*)(af)     = *(const float4*)&As[kk][ty * 8];
            *(float4*)(af + 4) = *(const float4*)&As[kk][ty * 8 + 4];
            *(float4*)(bf)     = *(const float4*)&Bs[kk][tx * 8];
            *(float4*)(bf + 4) = *(const float4*)&Bs[kk][tx * 8 + 4];
#pragma unroll
            for (int i = 0; i < 8; i++)
#pragma unroll
                for (int j = 0; j < 8; j++) acc[i][j] += af[i] * bf[j];
        }
    }
#pragma unroll
    for (int i = 0; i < 8; i++) {
        float* yr = Y + (size_t)(m0 + ty * 8 + i) * ldy + n0y + tx * 8;
        *(float4*)(yr)     = make_float4(acc[i][0], acc[i][1], acc[i][2], acc[i][3]);
        *(float4*)(yr + 4) = make_float4(acc[i][4], acc[i][5], acc[i][6], acc[i][7]);
    }
}

// Fused QKV GEMM: logical N = 1024 + 256 + 256 = 1536 (12 column tiles)
__global__ __launch_bounds__(256, 2) void qkv_gemm_kernel(
    const float* __restrict__ x, const float* __restrict__ wq,
    const float* __restrict__ wk, const float* __restrict__ wv)
{
    __shared__ float As[BK][BM];
    __shared__ float Bs[BK][BN];
    int n0 = blockIdx.y * BN;
    const float* W; float* Y; int n0w, ldy;
    if (n0 < CC)            { W = wq; Y = g_q; n0w = n0;            ldy = CC;  }
    else if (n0 < CC + KVD) { W = wk; Y = g_k; n0w = n0 - CC;       ldy = KVD; }
    else                    { W = wv; Y = g_v; n0w = n0 - CC - KVD; ldy = KVD; }
    gemm_tile(x, W, Y, ldy, blockIdx.x * BM, n0w, n0w, CC, As, Bs);
}

__global__ __launch_bounds__(256, 2) void proj_gemm_kernel(
    float* __restrict__ out, const float* __restrict__ wproj)
{
    __shared__ float As[BK][BM];
    __shared__ float Bs[BK][BN];
    gemm_tile(g_att, wproj, out, CC, blockIdx.x * BM,
              blockIdx.y * BN, blockIdx.y * BN, CC, As, Bs);
}

// ---------------- RMS norm + partial RoPE (one warp per head vector) --------
__global__ void norm_rope_kernel() {
    int gtid = blockIdx.x * blockDim.x + threadIdx.x;
    int task = gtid >> 5;                     // warp task id
    int lane = gtid & 31;
    const int NTASK = MM * (HH + HKVV);
    if (task >= NTASK) return;
    int row = task / (HH + HKVV);
    int hh  = task % (HH + HKVV);
    float* base = (hh < HH) ? (g_q + (size_t)row * CC + hh * DD)
                            : (g_k + (size_t)row * KVD + (hh - HH) * DD);
    float v0 = base[lane];
    float v1 = base[lane + 32];
    float ss = v0 * v0 + v1 * v1;
#pragma unroll
    for (int o = 16; o; o >>= 1) ss += __shfl_xor_sync(0xffffffffu, ss, o);
    float a = ss * (1.0f / 64.0f) + 1.1920929e-07f;   // eps = finfo(f32).eps
    float r = rsqrtf(a);
    r = r * (1.5f - 0.5f * a * r * r);                // Newton refine
    v0 *= r; v1 *= r;
    // partial RoPE on dims [0,16): pairs (d, d+8)
    int t = row % TT;
    float p = __shfl_xor_sync(0xffffffffu, v0, 8);
    if (lane < 16) {
        int i = lane & 7;
        float c = g_cos[t][i], s = g_sin[t][i];
        v0 = (lane < 8) ? (v0 * c + p * s) : (v0 * c - p * s);
    }
    base[lane] = v0;
    base[lane + 32] = v1;
}

// ---------------- flash attention (fp32, online softmax in log2 domain) -----
__global__ __launch_bounds__(128, 2) void attn_kernel(
    const float* __restrict__ qgain, const int* __restrict__ wl_ptr)
{
    __shared__ float Ksh[AK][DD];
    __shared__ float Vsh[AK][DD];

    int b  = blockIdx.z;
    int h  = blockIdx.y;
    int q0 = blockIdx.x * AQ;
    int tid = threadIdx.x;
    int kvh = h >> 2;                 // h / (H/Hkv)
    int qi  = q0 + tid;               // query position within sequence
    int row = b * TT + qi;

    int wl = *wl_ptr;
    if (wl < 0) wl = TT;              // no window

    // fold gain * 1/sqrt(D) * log2(e) into q  -> softmax in exp2 domain
    float qscale = qgain[h] * 0.125f * 1.4426950408889634f;

    float q[DD];
    {
        const float* qp = g_q + (size_t)row * CC + h * DD;
#pragma unroll
        for (int d = 0; d < DD; d += 4) {
            float4 t4 = *(const float4*)(qp + d);
            q[d] = t4.x * qscale; q[d+1] = t4.y * qscale;
            q[d+2] = t4.z * qscale; q[d+3] = t4.w * qscale;
        }
    }
    float o[DD];
#pragma unroll
    for (int d = 0; d < DD; d++) o[d] = 0.f;
    float mrun = -INFINITY, lrun = 0.f;

    int lo = q0 - wl;
    int kt_lo = (lo > 0) ? (lo / AK) : 0;
    int kt_hi = (q0 + AQ - 1) / AK;          // inclusive

    const float* kbase = g_k + (size_t)b * TT * KVD + kvh * DD;
    const float* vbase = g_v + (size_t)b * TT * KVD + kvh * DD;

#pragma unroll 1
    for (int kt = kt_lo; kt <= kt_hi; kt++) {
        int k0 = kt * AK;
        __syncthreads();
        {
            int r  = tid >> 1;
            int dq = (tid & 1) * 32;
            const float* kr = kbase + (size_t)(k0 + r) * KVD + dq;
            const float* vr = vbase + (size_t)(k0 + r) * KVD + dq;
#pragma unroll
            for (int j = 0; j < 32; j += 4) {
                *(float4*)&Ksh[r][dq + j] = *(const float4*)(kr + j);
                *(float4*)&Vsh[r][dq + j] = *(const float4*)(vr + j);
            }
        }
        __syncthreads();

#pragma unroll 1
        for (int c = 0; c < AK; c += 8) {
            if (k0 + c > qi) break;          // all further keys in tile are future
            float s[8];
#pragma unroll
            for (int j = 0; j < 8; j++) {
                float acc = 0.f;
#pragma unroll
                for (int d = 0; d < DD; d += 4) {
                    float4 k4 = *(const float4*)&Ksh[c + j][d];
                    acc += q[d] * k4.x + q[d+1] * k4.y
                         + q[d+2] * k4.z + q[d+3] * k4.w;
                }
                int kj = k0 + c + j;
                bool ok = (kj <= qi) && (qi - kj <= wl);
                s[j] = ok ? acc : -INFINITY;
            }
            float mc = s[0];
#pragma unroll
            for (int j = 1; j < 8; j++) mc = fmaxf(mc, s[j]);
            if (mc == -INFINITY) continue;   // whole chunk behind the window
            float mnew = fmaxf(mrun, mc);
            float corr = exp2f(mrun - mnew); // mrun=-inf -> 0, correct
            lrun *= corr;
#pragma unroll
            for (int d = 0; d < DD; d++) o[d] *= corr;
#pragma unroll
            for (int j = 0; j < 8; j++) {
                s[j] = exp2f(s[j] - mnew);   // masked -> exp2(-inf) = 0
                lrun += s[j];
            }
#pragma unroll
            for (int j = 0; j < 8; j++) {
#pragma unroll
                for (int d = 0; d < DD; d += 4) {
                    float4 v4 = *(const float4*)&Vsh[c + j][d];
                    o[d]   += s[j] * v4.x; o[d+1] += s[j] * v4.y;
                    o[d+2] += s[j] * v4.z; o[d+3] += s[j] * v4.w;
                }
            }
            mrun = mnew;
        }
    }

    float inv = 1.0f / lrun;
    float* op = g_att + (size_t)row * CC + h * DD;
#pragma unroll
    for (int d = 0; d < DD; d += 4) {
        *(float4*)(op + d) = make_float4(o[d]*inv, o[d+1]*inv, o[d+2]*inv, o[d+3]*inv);
    }
}

// ---------------- launch -----------------------------------------------------
extern "C" void kernel_launch(void* const* d_in, const int* in_sizes, int n_in,
                              void* d_out, int out_size) {
    const float* x     = (const float*)d_in[0];
    const float* wq    = (const float*)d_in[1];
    const float* wk    = (const float*)d_in[2];
    const float* wv    = (const float*)d_in[3];
    const float* wproj = (const float*)d_in[4];
    const float* qgain = (const float*)d_in[5];
    const int*   wl    = (const int*)d_in[6];
    float* out = (float*)d_out;

    rope_table_kernel<<<(TT * 8 + 255) / 256, 256>>>();

    dim3 g1(MM / BM, (CC + 2 * KVD) / BN);   // 32 x 12
    qkv_gemm_kernel<<<g1, 256>>>(x, wq, wk, wv);

    int ntask = MM * (HH + HKVV);
    norm_rope_kernel<<<(ntask * 32 + 255) / 256, 256>>>();

    dim3 g2(TT / AQ, HH, BB);                // 16 x 16 x 2
    attn_kernel<<<g2, 128>>>(qgain, wl);

    dim3 g3(MM / BM, CC / BN);               // 32 x 8
    proj_gemm_kernel<<<g3, 256>>>(out, wproj);
}